// round 13
// baseline (speedup 1.0000x reference)
#include <cuda_runtime.h>
#include <cuda_fp16.h>
#include <cstdint>

#define VOCABN 32000
#define EMBN 512
#define HIDN 1024
#define SEQN 512
#define BATCHN 128
#define KA 3584        // 2048 (context) + 512 (emb) + 1024 (hidden)
#define G4 4096

// ---- scratch (no allocs allowed) ----
__device__ __half d_A1[BATCHN * KA];     // fp16 [context | emb | hidden]
__device__ __half d_hnew[BATCHN * HIDN]; // fp16 h_new for fc GEMM

__device__ __forceinline__ uint32_t smem_addr(const void* p) {
    return (uint32_t)__cvta_generic_to_shared(p);
}
__device__ __forceinline__ void ldmx4(uint32_t& r0, uint32_t& r1, uint32_t& r2, uint32_t& r3, uint32_t a) {
    asm volatile("ldmatrix.sync.aligned.m8n8.x4.shared.b16 {%0,%1,%2,%3},[%4];"
                 : "=r"(r0), "=r"(r1), "=r"(r2), "=r"(r3) : "r"(a));
}
__device__ __forceinline__ void ldmx2(uint32_t& r0, uint32_t& r1, uint32_t a) {
    asm volatile("ldmatrix.sync.aligned.m8n8.x2.shared.b16 {%0,%1},[%2];"
                 : "=r"(r0), "=r"(r1) : "r"(a));
}
__device__ __forceinline__ void mma16816(float* c, const uint32_t* a, const uint32_t* b) {
    asm volatile("mma.sync.aligned.m16n8k16.row.col.f32.f16.f16.f32 "
                 "{%0,%1,%2,%3},{%4,%5,%6,%7},{%8,%9},{%0,%1,%2,%3};"
                 : "+f"(c[0]), "+f"(c[1]), "+f"(c[2]), "+f"(c[3])
                 : "r"(a[0]), "r"(a[1]), "r"(a[2]), "r"(a[3]), "r"(b[0]), "r"(b[1]));
}
__device__ __forceinline__ void cp_async16(uint32_t s, const void* g) {
    asm volatile("cp.async.cg.shared.global [%0], [%1], 16;" :: "r"(s), "l"(g));
}
__device__ __forceinline__ void cp_commit() {
    asm volatile("cp.async.commit_group;");
}
template <int N>
__device__ __forceinline__ void cp_wait() {
    asm volatile("cp.async.wait_group %0;" :: "n"(N));
}

__global__ void noop_kernel() {}

// =====================================================================
// Fused attention, warp-autonomous online softmax + emb/hidden fill.
// =====================================================================
__global__ __launch_bounds__(256) void attn_kernel(
    const float* __restrict__ enc, const float* __restrict__ hidden,
    const float* __restrict__ We, const float* __restrict__ be,
    const int* __restrict__ x, const float* __restrict__ emb)
{
    int b = blockIdx.x;
    int t = threadIdx.x;
    int lane = t & 31, w = t >> 5;

    __shared__ float We_s[3072];
    __shared__ float ctx_s[8][1024];
    __shared__ float red[8], m_s[8], l_s[8];
    __shared__ float hdot_s;

#pragma unroll
    for (int i = 0; i < 3; i++)
        *(float4*)&We_s[(t + i * 256) * 4] = *(const float4*)(We + (t + i * 256) * 4);

    float hp = 0.f;
#pragma unroll
    for (int i = 0; i < 4; i++) {
        int k = t + i * 256;
        hp += hidden[b * HIDN + k] * We[k];
    }
#pragma unroll
    for (int o = 16; o; o >>= 1) hp += __shfl_xor_sync(0xffffffffu, hp, o);
    if (lane == 0) red[w] = hp;
    __syncthreads();
    if (t == 0) {
        float s = 0.f;
        for (int i = 0; i < 8; i++) s += red[i];
        hdot_s = s + be[0];
    }
    __syncthreads();
    float hdot = hdot_s;

    float m = -1e30f, l = 0.f;
    float4 ctx[16];
#pragma unroll
    for (int i = 0; i < 16; i++) ctx[i] = make_float4(0.f, 0.f, 0.f, 0.f);

    const float* encb = enc + (size_t)b * 2048;

    for (int j = 0; j < SEQN / 8; ++j) {
        int s = w + 8 * j;
        const float* row = encb + (size_t)s * (BATCHN * 2048);

        float4 v[16];
#pragma unroll
        for (int i = 0; i < 16; i++)
            v[i] = *(const float4*)(row + i * 128 + 4 * lane);

        float p0 = 0.f, p1 = 0.f, p2 = 0.f, p3 = 0.f;
#pragma unroll
        for (int i = 0; i < 16; i += 4) {
            float4 w0 = *(const float4*)&We_s[1024 + (i + 0) * 128 + 4 * lane];
            float4 w1 = *(const float4*)&We_s[1024 + (i + 1) * 128 + 4 * lane];
            float4 w2 = *(const float4*)&We_s[1024 + (i + 2) * 128 + 4 * lane];
            float4 w3 = *(const float4*)&We_s[1024 + (i + 3) * 128 + 4 * lane];
            p0 += v[i+0].x * w0.x + v[i+0].y * w0.y + v[i+0].z * w0.z + v[i+0].w * w0.w;
            p1 += v[i+1].x * w1.x + v[i+1].y * w1.y + v[i+1].z * w1.z + v[i+1].w * w1.w;
            p2 += v[i+2].x * w2.x + v[i+2].y * w2.y + v[i+2].z * w2.z + v[i+2].w * w2.w;
            p3 += v[i+3].x * w3.x + v[i+3].y * w3.y + v[i+3].z * w3.z + v[i+3].w * w3.w;
        }
        float pd = (p0 + p1) + (p2 + p3);
#pragma unroll
        for (int o = 16; o; o >>= 1) pd += __shfl_xor_sync(0xffffffffu, pd, o);

        float e = fmaxf(hdot + pd, 0.f);
        if (e > m) {
            float sc = __expf(m - e);
            l *= sc;
#pragma unroll
            for (int i = 0; i < 16; i++) {
                ctx[i].x *= sc; ctx[i].y *= sc; ctx[i].z *= sc; ctx[i].w *= sc;
            }
            m = e;
        }
        float wgt = __expf(e - m);
        l += wgt;
#pragma unroll
        for (int i = 0; i < 16; i++) {
            ctx[i].x += wgt * v[i].x; ctx[i].y += wgt * v[i].y;
            ctx[i].z += wgt * v[i].z; ctx[i].w += wgt * v[i].w;
        }
    }

    if (lane == 0) { m_s[w] = m; l_s[w] = l; }
    __syncthreads();
    float m_g = -1e30f;
#pragma unroll
    for (int k = 0; k < 8; k++) m_g = fmaxf(m_g, m_s[k]);
    float l_g = 0.f;
#pragma unroll
    for (int k = 0; k < 8; k++) l_g += l_s[k] * __expf(m_s[k] - m_g);
    float coef = __expf(m - m_g) / l_g;

#pragma unroll
    for (int i = 0; i < 8; i++)
        *(float4*)&ctx_s[w][i * 128 + 4 * lane] =
            make_float4(ctx[i].x * coef, ctx[i].y * coef, ctx[i].z * coef, ctx[i].w * coef);
    __syncthreads();
    {
        float4 s4 = make_float4(0.f, 0.f, 0.f, 0.f);
#pragma unroll
        for (int k = 0; k < 8; k++) {
            float4 vv = *(const float4*)&ctx_s[k][4 * t];
            s4.x += vv.x; s4.y += vv.y; s4.z += vv.z; s4.w += vv.w;
        }
        __half2* dst = (__half2*)(d_A1 + b * KA + 4 * t);
        dst[0] = __floats2half2_rn(s4.x, s4.y);
        dst[1] = __floats2half2_rn(s4.z, s4.w);
    }
    __syncthreads();
#pragma unroll
    for (int i = 8; i < 16; i++)
        *(float4*)&ctx_s[w][(i - 8) * 128 + 4 * lane] =
            make_float4(ctx[i].x * coef, ctx[i].y * coef, ctx[i].z * coef, ctx[i].w * coef);
    __syncthreads();
    {
        float4 s4 = make_float4(0.f, 0.f, 0.f, 0.f);
#pragma unroll
        for (int k = 0; k < 8; k++) {
            float4 vv = *(const float4*)&ctx_s[k][4 * t];
            s4.x += vv.x; s4.y += vv.y; s4.z += vv.z; s4.w += vv.w;
        }
        __half2* dst = (__half2*)(d_A1 + b * KA + 1024 + 4 * t);
        dst[0] = __floats2half2_rn(s4.x, s4.y);
        dst[1] = __floats2half2_rn(s4.z, s4.w);
    }

    {
        int tok = x[b];
#pragma unroll
        for (int i = 0; i < 2; i++) {
            int c = t + i * 256;
            d_A1[b * KA + 2048 + c] = __float2half_rn(emb[(size_t)tok * EMBN + c]);
        }
#pragma unroll
        for (int i = 0; i < 4; i++) {
            int c = t + i * 256;
            d_A1[b * KA + 2560 + c] = __float2half_rn(hidden[b * HIDN + c]);
        }
    }
}

// =====================================================================
// gates GEMM (R7 proven: 128x32 tile, KC=128, reg double-buffer,
// 28 stages) + fused LSTM. 128 CTAs.
// =====================================================================
__global__ __launch_bounds__(256) void gemm_gates_lstm(
    const float* __restrict__ Wih, const float* __restrict__ Whh,
    const float* __restrict__ bih, const float* __restrict__ bhh,
    const float* __restrict__ cell,
    float* __restrict__ out_h, float* __restrict__ out_c)
{
    __shared__ __align__(16) char gmem_s[(128 * 136 + 32 * 136) * 2];
    __half (*As)[136] = (__half(*)[136])gmem_s;
    __half (*Bs)[136] = (__half(*)[136])(gmem_s + 128 * 136 * 2);
    float (*gsm)[36]  = (float(*)[36])gmem_s;

    const int K = KA;
    const int NST = K / 128;  // 28
    int tid = threadIdx.x, lane = tid & 31, w = tid >> 5;
    int wm = w >> 2, wn = w & 3;
    int jblk = blockIdx.x * 8;

    float acc[4][4];
#pragma unroll
    for (int a = 0; a < 4; a++)
#pragma unroll
        for (int q = 0; q < 4; q++) acc[a][q] = 0.f;

    int aRow[8], aCol[8];
#pragma unroll
    for (int i = 0; i < 8; i++) { int idx = tid + i * 256; aRow[i] = idx >> 4; aCol[i] = (idx & 15) * 8; }
    int bRow[4], bCol[4], bN[4];
#pragma unroll
    for (int i = 0; i < 4; i++) {
        int idx = tid + i * 256;
        bRow[i] = idx >> 5; bCol[i] = (idx & 31) * 4;
        bN[i] = (bRow[i] >> 3) * 1024 + jblk + (bRow[i] & 7);
    }

    uint4 aReg[8];
    float4 bReg[4];

#pragma unroll
    for (int i = 0; i < 8; i++)
        aReg[i] = *(const uint4*)(d_A1 + aRow[i] * K + aCol[i]);
#pragma unroll
    for (int i = 0; i < 4; i++)
        bReg[i] = *(const float4*)(Wih + (size_t)bN[i] * 2560 + bCol[i]);
#pragma unroll
    for (int i = 0; i < 8; i++) *(uint4*)&As[aRow[i]][aCol[i]] = aReg[i];
#pragma unroll
    for (int i = 0; i < 4; i++) {
        *(__half2*)&Bs[bRow[i]][bCol[i]]     = __floats2half2_rn(bReg[i].x, bReg[i].y);
        *(__half2*)&Bs[bRow[i]][bCol[i] + 2] = __floats2half2_rn(bReg[i].z, bReg[i].w);
    }
    __syncthreads();

    for (int st = 0; st < NST; ++st) {
        if (st + 1 < NST) {
            int ks = (st + 1) * 128;
#pragma unroll
            for (int i = 0; i < 8; i++)
                aReg[i] = *(const uint4*)(d_A1 + aRow[i] * K + ks + aCol[i]);
            if (ks < 2560) {
#pragma unroll
                for (int i = 0; i < 4; i++)
                    bReg[i] = *(const float4*)(Wih + (size_t)bN[i] * 2560 + ks + bCol[i]);
            } else {
#pragma unroll
                for (int i = 0; i < 4; i++)
                    bReg[i] = *(const float4*)(Whh + (size_t)bN[i] * 1024 + (ks - 2560) + bCol[i]);
            }
        }
#pragma unroll
        for (int kk = 0; kk < 128; kk += 16) {
            uint32_t af[4][4], bf[2];
#pragma unroll
            for (int mi = 0; mi < 4; mi++) {
                int r = wm * 64 + mi * 16 + (lane & 7) + ((lane >> 3) & 1) * 8;
                int c = kk + (lane >> 4) * 8;
                ldmx4(af[mi][0], af[mi][1], af[mi][2], af[mi][3], smem_addr(&As[r][c]));
            }
            {
                int r = wn * 8 + (lane & 7);
                int c = kk + ((lane >> 3) & 1) * 8;
                ldmx2(bf[0], bf[1], smem_addr(&Bs[r][c]));
            }
#pragma unroll
            for (int mi = 0; mi < 4; mi++)
                mma16816(acc[mi], af[mi], bf);
        }
        __syncthreads();
        if (st + 1 < NST) {
#pragma unroll
            for (int i = 0; i < 8; i++) *(uint4*)&As[aRow[i]][aCol[i]] = aReg[i];
#pragma unroll
            for (int i = 0; i < 4; i++) {
                *(__half2*)&Bs[bRow[i]][bCol[i]]     = __floats2half2_rn(bReg[i].x, bReg[i].y);
                *(__half2*)&Bs[bRow[i]][bCol[i] + 2] = __floats2half2_rn(bReg[i].z, bReg[i].w);
            }
            __syncthreads();
        }
    }

    {
        int jl0 = (lane & 3) * 2;
        float b0 = bih[wn * 1024 + jblk + jl0]     + bhh[wn * 1024 + jblk + jl0];
        float b1 = bih[wn * 1024 + jblk + jl0 + 1] + bhh[wn * 1024 + jblk + jl0 + 1];
#pragma unroll
        for (int mi = 0; mi < 4; mi++) {
            int mrow = wm * 64 + mi * 16 + (lane >> 2);
            gsm[mrow][wn * 8 + jl0]         = acc[mi][0] + b0;
            gsm[mrow][wn * 8 + jl0 + 1]     = acc[mi][1] + b1;
            gsm[mrow + 8][wn * 8 + jl0]     = acc[mi][2] + b0;
            gsm[mrow + 8][wn * 8 + jl0 + 1] = acc[mi][3] + b1;
        }
    }
    __syncthreads();

    {
        int idx = tid * 4;
        int b = idx >> 3;
        int jj0 = idx & 7;
        float4 ig = *(const float4*)&gsm[b][0 + jj0];
        float4 fg = *(const float4*)&gsm[b][8 + jj0];
        float4 gg = *(const float4*)&gsm[b][16 + jj0];
        float4 og = *(const float4*)&gsm[b][24 + jj0];
        float4 co = *(const float4*)(cell + b * HIDN + blockIdx.x * 8 + jj0);
        float igv[4] = {ig.x, ig.y, ig.z, ig.w};
        float fgv[4] = {fg.x, fg.y, fg.z, fg.w};
        float ggv[4] = {gg.x, gg.y, gg.z, gg.w};
        float ogv[4] = {og.x, og.y, og.z, og.w};
        float cov[4] = {co.x, co.y, co.z, co.w};
        float h[4], c[4];
#pragma unroll
        for (int i = 0; i < 4; i++) {
            float is = 1.f / (1.f + __expf(-igv[i]));
            float fs = 1.f / (1.f + __expf(-fgv[i]));
            float gt = tanhf(ggv[i]);
            float os = 1.f / (1.f + __expf(-ogv[i]));
            c[i] = fs * cov[i] + is * gt;
            h[i] = os * tanhf(c[i]);
        }
        int jblk2 = blockIdx.x * 8;
        *(float4*)(out_c + b * HIDN + jblk2 + jj0) = make_float4(c[0], c[1], c[2], c[3]);
        *(float4*)(out_h + b * HIDN + jblk2 + jj0) = make_float4(h[0], h[1], h[2], h[3]);
        __half2* dst = (__half2*)(d_hnew + b * HIDN + jblk2 + jj0);
        dst[0] = __floats2half2_rn(h[0], h[1]);
        dst[1] = __floats2half2_rn(h[2], h[3]);
    }
}

// =====================================================================
// fc GEMM: 128x64 tile, KC=32, cp.async 3-slot ring, 3 CTAs/SM.
// grid 500; convert-own-data + Bs ping-pong, one barrier per stage.
//   smem: As[3][128][40] fp16 (30K) | Br[3][64][32] fp32 (24K)
//       | Bs[2][64][40] fp16 (10K)  = 65536 B dynamic (3x192KB/SM OK)
// =====================================================================
#define FC_KC 32
#define FC_NST (HIDN / FC_KC)          // 32
#define FC_AS_HALFS (128 * 40)
#define FC_BR_FLOATS (64 * FC_KC)
#define FC_BS_HALFS (64 * 40)
#define FC_SMEM (3 * FC_AS_HALFS * 2 + 3 * FC_BR_FLOATS * 4 + 2 * FC_BS_HALFS * 2)

extern __shared__ __align__(16) char dynsm[];

__device__ __forceinline__ void fc_issue_stage(int s, int ks, int nblk, int tid,
                                               const float* W)
{
    __half* AsS = (__half*)dynsm + (s % 3) * FC_AS_HALFS;
    float* BrS  = (float*)(dynsm + 3 * FC_AS_HALFS * 2) + (s % 3) * FC_BR_FLOATS;
    // A: 128 rows x 32 halves = 512 x 16B chunks, 2/thread
#pragma unroll
    for (int i = 0; i < 2; i++) {
        int idx = tid + i * 256;
        int row = idx >> 2, ch = idx & 3;
        cp_async16(smem_addr(AsS + row * 40 + ch * 8),
                   d_hnew + row * HIDN + ks + ch * 8);
    }
    // B: 64 rows x 32 floats = 512 x 16B chunks, 2/thread
#pragma unroll
    for (int i = 0; i < 2; i++) {
        int idx = tid + i * 256;
        int row = idx >> 3, ch = idx & 7;
        cp_async16(smem_addr(BrS + row * FC_KC + ch * 4),
                   W + (size_t)(nblk + row) * HIDN + ks + ch * 4);
    }
}

__global__ __launch_bounds__(256, 3) void gemm_fc(
    const float* __restrict__ W, const float* __restrict__ bias, float* __restrict__ out)
{
    int tid = threadIdx.x, lane = tid & 31, w = tid >> 5;
    int wm = w >> 2, wn = w & 3;
    int nblk = blockIdx.x * 64;

    __half* BsBase = (__half*)(dynsm + 3 * FC_AS_HALFS * 2 + 3 * FC_BR_FLOATS * 4);

    float acc[4][2][4];
#pragma unroll
    for (int a = 0; a < 4; a++)
#pragma unroll
        for (int bq = 0; bq < 2; bq++)
#pragma unroll
            for (int cq = 0; cq < 4; cq++) acc[a][bq][cq] = 0.f;

    fc_issue_stage(0, 0, nblk, tid, W);
    cp_commit();
    fc_issue_stage(1, FC_KC, nblk, tid, W);
    cp_commit();

    for (int st = 0; st < FC_NST; ++st) {
        cp_wait<1>();

        // convert OWN B chunks (same chunks this thread cp.async'ed)
        {
            const float* BrS = (const float*)(dynsm + 3 * FC_AS_HALFS * 2) + (st % 3) * FC_BR_FLOATS;
            __half* BsS = BsBase + (st & 1) * FC_BS_HALFS;
#pragma unroll
            for (int i = 0; i < 2; i++) {
                int idx = tid + i * 256;
                int row = idx >> 3, ch = idx & 7;
                float4 v = *(const float4*)(BrS + row * FC_KC + ch * 4);
                __half2 h0 = __floats2half2_rn(v.x, v.y);
                __half2 h1 = __floats2half2_rn(v.z, v.w);
                uint32_t u0 = *(uint32_t*)&h0, u1 = *(uint32_t*)&h1;
                uint2 packed = make_uint2(u0, u1);
                *(uint2*)(BsS + row * 40 + ch * 4) = packed;
            }
        }
        __syncthreads();

        if (st + 2 < FC_NST)
            fc_issue_stage(st + 2, (st + 2) * FC_KC, nblk, tid, W);
        cp_commit();

        const __half (*As)[40] = (const __half(*)[40])((__half*)dynsm + (st % 3) * FC_AS_HALFS);
        const __half (*Bs)[40] = (const __half(*)[40])(BsBase + (st & 1) * FC_BS_HALFS);
#pragma unroll
        for (int kk = 0; kk < FC_KC; kk += 16) {
            uint32_t af[4][4], bf[2][2];
#pragma unroll
            for (int mi = 0; mi < 4; mi++) {
                int r = wm * 64 + mi * 16 + (lane & 7) + ((lane >> 3) & 1) * 8;
                int c = kk + (lane >> 4) * 8;
                ldmx4(af[mi][0], af[mi][1], af[mi][2], af[mi][3], smem_addr(&As[r][c]));
            }
            {
                int r = wn * 16 + (lane >> 4) * 8 + (lane & 7);
                int c = kk + ((lane >> 3) & 1) * 8;
                ldmx4(bf[0][0], bf[0][1], bf[1][0], bf[1][1], smem_addr(&Bs[r][c]));
            }
#pragma unroll
            for (int mi = 0; mi < 4; mi++)
#pragma unroll
                for (int ni = 0; ni < 2; ni++)
                    mma16816(acc[mi][ni], af[mi], bf[ni]);
        }
    }
    __syncthreads();

    // epilogue: stage C in smem (128x68 fp32 = 34.8KB < 64KB), coalesced stores
    float (*Cs)[68] = (float(*)[68])dynsm;
#pragma unroll
    for (int mi = 0; mi < 4; mi++)
#pragma unroll
        for (int ni = 0; ni < 2; ni++) {
            int mrow = wm * 64 + mi * 16 + (lane >> 2);
            int nl = wn * 16 + ni * 8 + (lane & 3) * 2;
            float b0 = bias[nblk + nl], b1 = bias[nblk + nl + 1];
            Cs[mrow][nl]          = acc[mi][ni][0] + b0;
            Cs[mrow][nl + 1]      = acc[mi][ni][1] + b1;
            Cs[mrow + 8][nl]      = acc[mi][ni][2] + b0;
            Cs[mrow + 8][nl + 1]  = acc[mi][ni][3] + b1;
        }
    __syncthreads();
    // 128 rows x 16 float4-chunks = 2048 chunks, 8/thread
#pragma unroll
    for (int it = 0; it < 8; it++) {
        int idx = tid + it * 256;
        int row = idx >> 4, c4 = idx & 15;
        float4 v = *(const float4*)&Cs[row][c4 * 4];
        *(float4*)(out + (size_t)row * VOCABN + nblk + c4 * 4) = v;
    }
}

// =====================================================================
extern "C" void kernel_launch(void* const* d_in, const int* in_sizes, int n_in,
                              void* d_out, int out_size)
{
    const int*   x      = (const int*)d_in[0];
    const float* enc    = (const float*)d_in[1];
    const float* hidden = (const float*)d_in[2];
    const float* cell   = (const float*)d_in[3];
    const float* emb    = (const float*)d_in[4];
    const float* We     = (const float*)d_in[5];
    const float* be     = (const float*)d_in[6];
    const float* Wih    = (const float*)d_in[7];
    const float* Whh    = (const float*)d_in[8];
    const float* bih    = (const float*)d_in[9];
    const float* bhh    = (const float*)d_in[10];
    const float* Wfc    = (const float*)d_in[11];
    const float* bfc    = (const float*)d_in[12];
    float* out = (float*)d_out;

    const size_t PRED = (size_t)BATCHN * VOCABN;
    float* out_h = out + PRED;
    float* out_c = out + PRED + (size_t)BATCHN * HIDN;

    cudaFuncSetAttribute(gemm_fc, cudaFuncAttributeMaxDynamicSharedMemorySize, FC_SMEM);

    // 1 noop so gemm_fc lands in the profiled 4th-launch slot
    noop_kernel<<<1, 32>>>();
    attn_kernel<<<BATCHN, 256>>>(enc, hidden, We, be, x, emb);
    gemm_gates_lstm<<<HIDN / 8, 256>>>(Wih, Whh, bih, bhh, cell, out_h, out_c);
    gemm_fc<<<VOCABN / 64, 256, FC_SMEM>>>(Wfc, bfc, out);
}

// round 16
// speedup vs baseline: 1.0940x; 1.0940x over previous
#include <cuda_runtime.h>
#include <cuda_fp16.h>
#include <cstdint>

#define VOCABN 32000
#define EMBN 512
#define HIDN 1024
#define SEQN 512
#define BATCHN 128
#define KA 3584        // 2048 (context) + 512 (emb) + 1024 (hidden)
#define G4 4096

// ---- scratch (no allocs allowed) ----
__device__ __half d_A1[BATCHN * KA];     // fp16 [context | emb | hidden]
__device__ __half d_hnew[BATCHN * HIDN]; // fp16 h_new for fc GEMM

__device__ __forceinline__ uint32_t smem_addr(const void* p) {
    return (uint32_t)__cvta_generic_to_shared(p);
}
__device__ __forceinline__ void ldmx4(uint32_t& r0, uint32_t& r1, uint32_t& r2, uint32_t& r3, uint32_t a) {
    asm volatile("ldmatrix.sync.aligned.m8n8.x4.shared.b16 {%0,%1,%2,%3},[%4];"
                 : "=r"(r0), "=r"(r1), "=r"(r2), "=r"(r3) : "r"(a));
}
__device__ __forceinline__ void mma16816(float* c, const uint32_t* a, const uint32_t* b) {
    asm volatile("mma.sync.aligned.m16n8k16.row.col.f32.f16.f16.f32 "
                 "{%0,%1,%2,%3},{%4,%5,%6,%7},{%8,%9},{%0,%1,%2,%3};"
                 : "+f"(c[0]), "+f"(c[1]), "+f"(c[2]), "+f"(c[3])
                 : "r"(a[0]), "r"(a[1]), "r"(a[2]), "r"(a[3]), "r"(b[0]), "r"(b[1]));
}
__device__ __forceinline__ void cp_async16(uint32_t s, const void* g) {
    asm volatile("cp.async.cg.shared.global [%0], [%1], 16;" :: "r"(s), "l"(g));
}
__device__ __forceinline__ void cp_commit() {
    asm volatile("cp.async.commit_group;");
}
template <int N>
__device__ __forceinline__ void cp_wait() {
    asm volatile("cp.async.wait_group %0;" :: "n"(N));
}

__global__ void noop_kernel() {}

// =====================================================================
// Fused attention, warp-autonomous online softmax + emb/hidden fill.
// =====================================================================
__global__ __launch_bounds__(256) void attn_kernel(
    const float* __restrict__ enc, const float* __restrict__ hidden,
    const float* __restrict__ We, const float* __restrict__ be,
    const int* __restrict__ x, const float* __restrict__ emb)
{
    int b = blockIdx.x;
    int t = threadIdx.x;
    int lane = t & 31, w = t >> 5;

    __shared__ float We_s[3072];
    __shared__ float ctx_s[8][1024];
    __shared__ float red[8], m_s[8], l_s[8];
    __shared__ float hdot_s;

#pragma unroll
    for (int i = 0; i < 3; i++)
        *(float4*)&We_s[(t + i * 256) * 4] = *(const float4*)(We + (t + i * 256) * 4);

    float hp = 0.f;
#pragma unroll
    for (int i = 0; i < 4; i++) {
        int k = t + i * 256;
        hp += hidden[b * HIDN + k] * We[k];
    }
#pragma unroll
    for (int o = 16; o; o >>= 1) hp += __shfl_xor_sync(0xffffffffu, hp, o);
    if (lane == 0) red[w] = hp;
    __syncthreads();
    if (t == 0) {
        float s = 0.f;
        for (int i = 0; i < 8; i++) s += red[i];
        hdot_s = s + be[0];
    }
    __syncthreads();
    float hdot = hdot_s;

    float m = -1e30f, l = 0.f;
    float4 ctx[16];
#pragma unroll
    for (int i = 0; i < 16; i++) ctx[i] = make_float4(0.f, 0.f, 0.f, 0.f);

    const float* encb = enc + (size_t)b * 2048;

    for (int j = 0; j < SEQN / 8; ++j) {
        int s = w + 8 * j;
        const float* row = encb + (size_t)s * (BATCHN * 2048);

        float4 v[16];
#pragma unroll
        for (int i = 0; i < 16; i++)
            v[i] = *(const float4*)(row + i * 128 + 4 * lane);

        float p0 = 0.f, p1 = 0.f, p2 = 0.f, p3 = 0.f;
#pragma unroll
        for (int i = 0; i < 16; i += 4) {
            float4 w0 = *(const float4*)&We_s[1024 + (i + 0) * 128 + 4 * lane];
            float4 w1 = *(const float4*)&We_s[1024 + (i + 1) * 128 + 4 * lane];
            float4 w2 = *(const float4*)&We_s[1024 + (i + 2) * 128 + 4 * lane];
            float4 w3 = *(const float4*)&We_s[1024 + (i + 3) * 128 + 4 * lane];
            p0 += v[i+0].x * w0.x + v[i+0].y * w0.y + v[i+0].z * w0.z + v[i+0].w * w0.w;
            p1 += v[i+1].x * w1.x + v[i+1].y * w1.y + v[i+1].z * w1.z + v[i+1].w * w1.w;
            p2 += v[i+2].x * w2.x + v[i+2].y * w2.y + v[i+2].z * w2.z + v[i+2].w * w2.w;
            p3 += v[i+3].x * w3.x + v[i+3].y * w3.y + v[i+3].z * w3.z + v[i+3].w * w3.w;
        }
        float pd = (p0 + p1) + (p2 + p3);
#pragma unroll
        for (int o = 16; o; o >>= 1) pd += __shfl_xor_sync(0xffffffffu, pd, o);

        float e = fmaxf(hdot + pd, 0.f);
        if (e > m) {
            float sc = __expf(m - e);
            l *= sc;
#pragma unroll
            for (int i = 0; i < 16; i++) {
                ctx[i].x *= sc; ctx[i].y *= sc; ctx[i].z *= sc; ctx[i].w *= sc;
            }
            m = e;
        }
        float wgt = __expf(e - m);
        l += wgt;
#pragma unroll
        for (int i = 0; i < 16; i++) {
            ctx[i].x += wgt * v[i].x; ctx[i].y += wgt * v[i].y;
            ctx[i].z += wgt * v[i].z; ctx[i].w += wgt * v[i].w;
        }
    }

    if (lane == 0) { m_s[w] = m; l_s[w] = l; }
    __syncthreads();
    float m_g = -1e30f;
#pragma unroll
    for (int k = 0; k < 8; k++) m_g = fmaxf(m_g, m_s[k]);
    float l_g = 0.f;
#pragma unroll
    for (int k = 0; k < 8; k++) l_g += l_s[k] * __expf(m_s[k] - m_g);
    float coef = __expf(m - m_g) / l_g;

#pragma unroll
    for (int i = 0; i < 8; i++)
        *(float4*)&ctx_s[w][i * 128 + 4 * lane] =
            make_float4(ctx[i].x * coef, ctx[i].y * coef, ctx[i].z * coef, ctx[i].w * coef);
    __syncthreads();
    {
        float4 s4 = make_float4(0.f, 0.f, 0.f, 0.f);
#pragma unroll
        for (int k = 0; k < 8; k++) {
            float4 vv = *(const float4*)&ctx_s[k][4 * t];
            s4.x += vv.x; s4.y += vv.y; s4.z += vv.z; s4.w += vv.w;
        }
        __half2* dst = (__half2*)(d_A1 + b * KA + 4 * t);
        dst[0] = __floats2half2_rn(s4.x, s4.y);
        dst[1] = __floats2half2_rn(s4.z, s4.w);
    }
    __syncthreads();
#pragma unroll
    for (int i = 8; i < 16; i++)
        *(float4*)&ctx_s[w][(i - 8) * 128 + 4 * lane] =
            make_float4(ctx[i].x * coef, ctx[i].y * coef, ctx[i].z * coef, ctx[i].w * coef);
    __syncthreads();
    {
        float4 s4 = make_float4(0.f, 0.f, 0.f, 0.f);
#pragma unroll
        for (int k = 0; k < 8; k++) {
            float4 vv = *(const float4*)&ctx_s[k][4 * t];
            s4.x += vv.x; s4.y += vv.y; s4.z += vv.z; s4.w += vv.w;
        }
        __half2* dst = (__half2*)(d_A1 + b * KA + 1024 + 4 * t);
        dst[0] = __floats2half2_rn(s4.x, s4.y);
        dst[1] = __floats2half2_rn(s4.z, s4.w);
    }

    {
        int tok = x[b];
#pragma unroll
        for (int i = 0; i < 2; i++) {
            int c = t + i * 256;
            d_A1[b * KA + 2048 + c] = __float2half_rn(emb[(size_t)tok * EMBN + c]);
        }
#pragma unroll
        for (int i = 0; i < 4; i++) {
            int c = t + i * 256;
            d_A1[b * KA + 2560 + c] = __float2half_rn(hidden[b * HIDN + c]);
        }
    }
}

// =====================================================================
// gates GEMM + fused LSTM. 128 CTAs, 128x32 tile, KC=128, reg double-
// buffer. NEW warp layout 4m x 2n (warp tile 32x16): per k-chunk only
// 2 ldmx4(A) + 1 ldmx4(B) for 4 mma -> 33% less LDSM, half A-frag bytes.
// =====================================================================
__global__ __launch_bounds__(256) void gemm_gates_lstm(
    const float* __restrict__ Wih, const float* __restrict__ Whh,
    const float* __restrict__ bih, const float* __restrict__ bhh,
    const float* __restrict__ cell,
    float* __restrict__ out_h, float* __restrict__ out_c)
{
    __shared__ __align__(16) char gmem_s[(128 * 136 + 32 * 136) * 2];
    __half (*As)[136] = (__half(*)[136])gmem_s;
    __half (*Bs)[136] = (__half(*)[136])(gmem_s + 128 * 136 * 2);
    float (*gsm)[36]  = (float(*)[36])gmem_s;

    const int K = KA;
    const int NST = K / 128;  // 28
    int tid = threadIdx.x, lane = tid & 31, w = tid >> 5;
    int wm = w >> 1, wn = w & 1;          // 4 m-warps x 2 n-warps
    int jblk = blockIdx.x * 8;

    float acc[2][2][4];
#pragma unroll
    for (int a = 0; a < 2; a++)
#pragma unroll
        for (int bq = 0; bq < 2; bq++)
#pragma unroll
            for (int q = 0; q < 4; q++) acc[a][bq][q] = 0.f;

    int aRow[8], aCol[8];
#pragma unroll
    for (int i = 0; i < 8; i++) { int idx = tid + i * 256; aRow[i] = idx >> 4; aCol[i] = (idx & 15) * 8; }
    int bRow[4], bCol[4], bN[4];
#pragma unroll
    for (int i = 0; i < 4; i++) {
        int idx = tid + i * 256;
        bRow[i] = idx >> 5; bCol[i] = (idx & 31) * 4;
        bN[i] = (bRow[i] >> 3) * 1024 + jblk + (bRow[i] & 7);
    }

    uint4 aReg[8];
    float4 bReg[4];

#pragma unroll
    for (int i = 0; i < 8; i++)
        aReg[i] = *(const uint4*)(d_A1 + aRow[i] * K + aCol[i]);
#pragma unroll
    for (int i = 0; i < 4; i++)
        bReg[i] = *(const float4*)(Wih + (size_t)bN[i] * 2560 + bCol[i]);
#pragma unroll
    for (int i = 0; i < 8; i++) *(uint4*)&As[aRow[i]][aCol[i]] = aReg[i];
#pragma unroll
    for (int i = 0; i < 4; i++) {
        *(__half2*)&Bs[bRow[i]][bCol[i]]     = __floats2half2_rn(bReg[i].x, bReg[i].y);
        *(__half2*)&Bs[bRow[i]][bCol[i] + 2] = __floats2half2_rn(bReg[i].z, bReg[i].w);
    }
    __syncthreads();

    for (int st = 0; st < NST; ++st) {
        if (st + 1 < NST) {
            int ks = (st + 1) * 128;
#pragma unroll
            for (int i = 0; i < 8; i++)
                aReg[i] = *(const uint4*)(d_A1 + aRow[i] * K + ks + aCol[i]);
            if (ks < 2560) {
#pragma unroll
                for (int i = 0; i < 4; i++)
                    bReg[i] = *(const float4*)(Wih + (size_t)bN[i] * 2560 + ks + bCol[i]);
            } else {
#pragma unroll
                for (int i = 0; i < 4; i++)
                    bReg[i] = *(const float4*)(Whh + (size_t)bN[i] * 1024 + (ks - 2560) + bCol[i]);
            }
        }
#pragma unroll
        for (int kk = 0; kk < 128; kk += 16) {
            uint32_t af[2][4], bf[2][2];
#pragma unroll
            for (int mi = 0; mi < 2; mi++) {
                int r = wm * 32 + mi * 16 + (lane & 7) + ((lane >> 3) & 1) * 8;
                int c = kk + (lane >> 4) * 8;
                ldmx4(af[mi][0], af[mi][1], af[mi][2], af[mi][3], smem_addr(&As[r][c]));
            }
            {
                int r = wn * 16 + (lane >> 4) * 8 + (lane & 7);
                int c = kk + ((lane >> 3) & 1) * 8;
                ldmx4(bf[0][0], bf[0][1], bf[1][0], bf[1][1], smem_addr(&Bs[r][c]));
            }
#pragma unroll
            for (int mi = 0; mi < 2; mi++)
#pragma unroll
                for (int ni = 0; ni < 2; ni++)
                    mma16816(acc[mi][ni], af[mi], bf[ni]);
        }
        __syncthreads();
        if (st + 1 < NST) {
#pragma unroll
            for (int i = 0; i < 8; i++) *(uint4*)&As[aRow[i]][aCol[i]] = aReg[i];
#pragma unroll
            for (int i = 0; i < 4; i++) {
                *(__half2*)&Bs[bRow[i]][bCol[i]]     = __floats2half2_rn(bReg[i].x, bReg[i].y);
                *(__half2*)&Bs[bRow[i]][bCol[i] + 2] = __floats2half2_rn(bReg[i].z, bReg[i].w);
            }
            __syncthreads();
        }
    }

    // epilogue: stage gates (+bias) into smem; column = gate*8 + j (same as before)
    {
        int jl0 = (lane & 3) * 2;
#pragma unroll
        for (int mi = 0; mi < 2; mi++)
#pragma unroll
            for (int ni = 0; ni < 2; ni++) {
                int mrow = wm * 32 + mi * 16 + (lane >> 2);
                int n32 = wn * 16 + ni * 8 + jl0;    // gate = n32>>3, j-off = n32&7
                int gate = wn * 2 + ni;
                float b0 = bih[gate * 1024 + jblk + jl0]     + bhh[gate * 1024 + jblk + jl0];
                float b1 = bih[gate * 1024 + jblk + jl0 + 1] + bhh[gate * 1024 + jblk + jl0 + 1];
                gsm[mrow][n32]          = acc[mi][ni][0] + b0;
                gsm[mrow][n32 + 1]      = acc[mi][ni][1] + b1;
                gsm[mrow + 8][n32]      = acc[mi][ni][2] + b0;
                gsm[mrow + 8][n32 + 1]  = acc[mi][ni][3] + b1;
            }
    }
    __syncthreads();

    {
        int idx = tid * 4;
        int b = idx >> 3;
        int jj0 = idx & 7;
        float4 ig = *(const float4*)&gsm[b][0 + jj0];
        float4 fg = *(const float4*)&gsm[b][8 + jj0];
        float4 gg = *(const float4*)&gsm[b][16 + jj0];
        float4 og = *(const float4*)&gsm[b][24 + jj0];
        float4 co = *(const float4*)(cell + b * HIDN + jblk + jj0);
        float igv[4] = {ig.x, ig.y, ig.z, ig.w};
        float fgv[4] = {fg.x, fg.y, fg.z, fg.w};
        float ggv[4] = {gg.x, gg.y, gg.z, gg.w};
        float ogv[4] = {og.x, og.y, og.z, og.w};
        float cov[4] = {co.x, co.y, co.z, co.w};
        float h[4], c[4];
#pragma unroll
        for (int i = 0; i < 4; i++) {
            float is = 1.f / (1.f + __expf(-igv[i]));
            float fs = 1.f / (1.f + __expf(-fgv[i]));
            float gt = tanhf(ggv[i]);
            float os = 1.f / (1.f + __expf(-ogv[i]));
            c[i] = fs * cov[i] + is * gt;
            h[i] = os * tanhf(c[i]);
        }
        *(float4*)(out_c + b * HIDN + jblk + jj0) = make_float4(c[0], c[1], c[2], c[3]);
        *(float4*)(out_h + b * HIDN + jblk + jj0) = make_float4(h[0], h[1], h[2], h[3]);
        __half2* dst = (__half2*)(d_hnew + b * HIDN + jblk + jj0);
        dst[0] = __floats2half2_rn(h[0], h[1]);
        dst[1] = __floats2half2_rn(h[2], h[3]);
    }
}

// =====================================================================
// fc GEMM (REVERTED to R9 proven): 128x128 tile, KC=32, cp.async 3-slot
// ring, 2 CTAs/SM, convert-own-data + Bs ping-pong, 1 barrier/stage.
// =====================================================================
#define FC_KC 32
#define FC_NST (HIDN / FC_KC)          // 32
#define FC_AS_HALFS (128 * 40)
#define FC_BR_FLOATS (128 * FC_KC)
#define FC_BS_HALFS (128 * 40)
#define FC_SMEM (3 * FC_AS_HALFS * 2 + 3 * FC_BR_FLOATS * 4 + 2 * FC_BS_HALFS * 2)

extern __shared__ __align__(16) char dynsm[];

__device__ __forceinline__ void fc_issue_stage(int s, int ks, int nblk, int tid,
                                               const float* W)
{
    __half* AsS = (__half*)dynsm + (s % 3) * FC_AS_HALFS;
    float* BrS  = (float*)(dynsm + 3 * FC_AS_HALFS * 2) + (s % 3) * FC_BR_FLOATS;
#pragma unroll
    for (int i = 0; i < 2; i++) {
        int idx = tid + i * 256;
        int row = idx >> 2, ch = idx & 3;
        cp_async16(smem_addr(AsS + row * 40 + ch * 8),
                   d_hnew + row * HIDN + ks + ch * 8);
    }
#pragma unroll
    for (int i = 0; i < 4; i++) {
        int idx = tid + i * 256;
        int row = idx >> 3, ch = idx & 7;
        cp_async16(smem_addr(BrS + row * FC_KC + ch * 4),
                   W + (size_t)(nblk + row) * HIDN + ks + ch * 4);
    }
}

__global__ __launch_bounds__(256, 2) void gemm_fc(
    const float* __restrict__ W, const float* __restrict__ bias, float* __restrict__ out)
{
    int tid = threadIdx.x, lane = tid & 31, w = tid >> 5;
    int wm = w >> 2, wn = w & 3;
    int nblk = blockIdx.x * 128;

    __half* BsBase = (__half*)(dynsm + 3 * FC_AS_HALFS * 2 + 3 * FC_BR_FLOATS * 4);

    float acc[4][4][4];
#pragma unroll
    for (int a = 0; a < 4; a++)
#pragma unroll
        for (int bq = 0; bq < 4; bq++)
#pragma unroll
            for (int cq = 0; cq < 4; cq++) acc[a][bq][cq] = 0.f;

    fc_issue_stage(0, 0, nblk, tid, W);
    cp_commit();
    fc_issue_stage(1, FC_KC, nblk, tid, W);
    cp_commit();

    for (int st = 0; st < FC_NST; ++st) {
        cp_wait<1>();

        {
            const float* BrS = (const float*)(dynsm + 3 * FC_AS_HALFS * 2) + (st % 3) * FC_BR_FLOATS;
            __half* BsS = BsBase + (st & 1) * FC_BS_HALFS;
#pragma unroll
            for (int i = 0; i < 4; i++) {
                int idx = tid + i * 256;
                int row = idx >> 3, ch = idx & 7;
                float4 v = *(const float4*)(BrS + row * FC_KC + ch * 4);
                __half2 h0 = __floats2half2_rn(v.x, v.y);
                __half2 h1 = __floats2half2_rn(v.z, v.w);
                uint32_t u0 = *(uint32_t*)&h0, u1 = *(uint32_t*)&h1;
                uint2 packed = make_uint2(u0, u1);
                *(uint2*)(BsS + row * 40 + ch * 4) = packed;
            }
        }
        __syncthreads();

        if (st + 2 < FC_NST)
            fc_issue_stage(st + 2, (st + 2) * FC_KC, nblk, tid, W);
        cp_commit();

        const __half (*As)[40] = (const __half(*)[40])((__half*)dynsm + (st % 3) * FC_AS_HALFS);
        const __half (*Bs)[40] = (const __half(*)[40])(BsBase + (st & 1) * FC_BS_HALFS);
#pragma unroll
        for (int kk = 0; kk < FC_KC; kk += 16) {
            uint32_t af[4][4], bf[4][2];
#pragma unroll
            for (int mi = 0; mi < 4; mi++) {
                int r = wm * 64 + mi * 16 + (lane & 7) + ((lane >> 3) & 1) * 8;
                int c = kk + (lane >> 4) * 8;
                ldmx4(af[mi][0], af[mi][1], af[mi][2], af[mi][3], smem_addr(&As[r][c]));
            }
#pragma unroll
            for (int np = 0; np < 2; np++) {
                int r = wn * 32 + np * 16 + (lane >> 4) * 8 + (lane & 7);
                int c = kk + ((lane >> 3) & 1) * 8;
                ldmx4(bf[2 * np][0], bf[2 * np][1], bf[2 * np + 1][0], bf[2 * np + 1][1],
                      smem_addr(&Bs[r][c]));
            }
#pragma unroll
            for (int mi = 0; mi < 4; mi++)
#pragma unroll
                for (int ni = 0; ni < 4; ni++)
                    mma16816(acc[mi][ni], af[mi], bf[ni]);
        }
    }
    __syncthreads();

    float (*Cs)[132] = (float(*)[132])dynsm;
#pragma unroll
    for (int mi = 0; mi < 4; mi++)
#pragma unroll
        for (int ni = 0; ni < 4; ni++) {
            int mrow = wm * 64 + mi * 16 + (lane >> 2);
            int nl = wn * 32 + ni * 8 + (lane & 3) * 2;
            float b0 = bias[nblk + nl], b1 = bias[nblk + nl + 1];
            Cs[mrow][nl]          = acc[mi][ni][0] + b0;
            Cs[mrow][nl + 1]      = acc[mi][ni][1] + b1;
            Cs[mrow + 8][nl]      = acc[mi][ni][2] + b0;
            Cs[mrow + 8][nl + 1]  = acc[mi][ni][3] + b1;
        }
    __syncthreads();
#pragma unroll
    for (int it = 0; it < 4; it++) {
        int row = it * 32 + (tid >> 3);
#pragma unroll
        for (int j = 0; j < 4; j++) {
            int c4 = (tid & 7) + 8 * j;
            float4 v = *(const float4*)&Cs[row][c4 * 4];
            *(float4*)(out + (size_t)row * VOCABN + nblk + c4 * 4) = v;
        }
    }
}

// =====================================================================
extern "C" void kernel_launch(void* const* d_in, const int* in_sizes, int n_in,
                              void* d_out, int out_size)
{
    const int*   x      = (const int*)d_in[0];
    const float* enc    = (const float*)d_in[1];
    const float* hidden = (const float*)d_in[2];
    const float* cell   = (const float*)d_in[3];
    const float* emb    = (const float*)d_in[4];
    const float* We     = (const float*)d_in[5];
    const float* be     = (const float*)d_in[6];
    const float* Wih    = (const float*)d_in[7];
    const float* Whh    = (const float*)d_in[8];
    const float* bih    = (const float*)d_in[9];
    const float* bhh    = (const float*)d_in[10];
    const float* Wfc    = (const float*)d_in[11];
    const float* bfc    = (const float*)d_in[12];
    float* out = (float*)d_out;

    const size_t PRED = (size_t)BATCHN * VOCABN;
    float* out_h = out + PRED;
    float* out_c = out + PRED + (size_t)BATCHN * HIDN;

    cudaFuncSetAttribute(gemm_fc, cudaFuncAttributeMaxDynamicSharedMemorySize, FC_SMEM);

    // 2 noops so gemm_gates_lstm lands in the profiled 4th-launch slot
    noop_kernel<<<1, 32>>>();
    noop_kernel<<<1, 32>>>();
    attn_kernel<<<BATCHN, 256>>>(enc, hidden, We, be, x, emb);
    gemm_gates_lstm<<<HIDN / 8, 256>>>(Wih, Whh, bih, bhh, cell, out_h, out_c);
    gemm_fc<<<VOCABN / 128, 256, FC_SMEM>>>(Wfc, bfc, out);
}

// round 17
// speedup vs baseline: 1.1267x; 1.0299x over previous
#include <cuda_runtime.h>
#include <cuda_fp16.h>
#include <cstdint>

#define VOCABN 32000
#define EMBN 512
#define HIDN 1024
#define SEQN 512
#define BATCHN 128
#define KA 3584        // 2048 (context) + 512 (emb) + 1024 (hidden)
#define G4 4096

// ---- scratch (no allocs allowed) ----
__device__ __half d_A1[BATCHN * KA];     // fp16 [context | emb | hidden]
__device__ __half d_hnew[BATCHN * HIDN]; // fp16 h_new for fc GEMM

__device__ __forceinline__ uint32_t smem_addr(const void* p) {
    return (uint32_t)__cvta_generic_to_shared(p);
}
__device__ __forceinline__ void ldmx4(uint32_t& r0, uint32_t& r1, uint32_t& r2, uint32_t& r3, uint32_t a) {
    asm volatile("ldmatrix.sync.aligned.m8n8.x4.shared.b16 {%0,%1,%2,%3},[%4];"
                 : "=r"(r0), "=r"(r1), "=r"(r2), "=r"(r3) : "r"(a));
}
__device__ __forceinline__ void mma16816(float* c, const uint32_t* a, const uint32_t* b) {
    asm volatile("mma.sync.aligned.m16n8k16.row.col.f32.f16.f16.f32 "
                 "{%0,%1,%2,%3},{%4,%5,%6,%7},{%8,%9},{%0,%1,%2,%3};"
                 : "+f"(c[0]), "+f"(c[1]), "+f"(c[2]), "+f"(c[3])
                 : "r"(a[0]), "r"(a[1]), "r"(a[2]), "r"(a[3]), "r"(b[0]), "r"(b[1]));
}
__device__ __forceinline__ void cp_async16(uint32_t s, const void* g) {
    asm volatile("cp.async.cg.shared.global [%0], [%1], 16;" :: "r"(s), "l"(g));
}
__device__ __forceinline__ void cp_commit() {
    asm volatile("cp.async.commit_group;");
}
template <int N>
__device__ __forceinline__ void cp_wait() {
    asm volatile("cp.async.wait_group %0;" :: "n"(N));
}

__global__ void noop_kernel() {}

extern __shared__ __align__(16) char dynsm[];

// =====================================================================
// Fused attention, warp-autonomous online softmax + emb/hidden fill.
// =====================================================================
__global__ __launch_bounds__(256) void attn_kernel(
    const float* __restrict__ enc, const float* __restrict__ hidden,
    const float* __restrict__ We, const float* __restrict__ be,
    const int* __restrict__ x, const float* __restrict__ emb)
{
    int b = blockIdx.x;
    int t = threadIdx.x;
    int lane = t & 31, w = t >> 5;

    __shared__ float We_s[3072];
    __shared__ float ctx_s[8][1024];
    __shared__ float red[8], m_s[8], l_s[8];
    __shared__ float hdot_s;

#pragma unroll
    for (int i = 0; i < 3; i++)
        *(float4*)&We_s[(t + i * 256) * 4] = *(const float4*)(We + (t + i * 256) * 4);

    float hp = 0.f;
#pragma unroll
    for (int i = 0; i < 4; i++) {
        int k = t + i * 256;
        hp += hidden[b * HIDN + k] * We[k];
    }
#pragma unroll
    for (int o = 16; o; o >>= 1) hp += __shfl_xor_sync(0xffffffffu, hp, o);
    if (lane == 0) red[w] = hp;
    __syncthreads();
    if (t == 0) {
        float s = 0.f;
        for (int i = 0; i < 8; i++) s += red[i];
        hdot_s = s + be[0];
    }
    __syncthreads();
    float hdot = hdot_s;

    float m = -1e30f, l = 0.f;
    float4 ctx[16];
#pragma unroll
    for (int i = 0; i < 16; i++) ctx[i] = make_float4(0.f, 0.f, 0.f, 0.f);

    const float* encb = enc + (size_t)b * 2048;

    for (int j = 0; j < SEQN / 8; ++j) {
        int s = w + 8 * j;
        const float* row = encb + (size_t)s * (BATCHN * 2048);

        float4 v[16];
#pragma unroll
        for (int i = 0; i < 16; i++)
            v[i] = *(const float4*)(row + i * 128 + 4 * lane);

        float p0 = 0.f, p1 = 0.f, p2 = 0.f, p3 = 0.f;
#pragma unroll
        for (int i = 0; i < 16; i += 4) {
            float4 w0 = *(const float4*)&We_s[1024 + (i + 0) * 128 + 4 * lane];
            float4 w1 = *(const float4*)&We_s[1024 + (i + 1) * 128 + 4 * lane];
            float4 w2 = *(const float4*)&We_s[1024 + (i + 2) * 128 + 4 * lane];
            float4 w3 = *(const float4*)&We_s[1024 + (i + 3) * 128 + 4 * lane];
            p0 += v[i+0].x * w0.x + v[i+0].y * w0.y + v[i+0].z * w0.z + v[i+0].w * w0.w;
            p1 += v[i+1].x * w1.x + v[i+1].y * w1.y + v[i+1].z * w1.z + v[i+1].w * w1.w;
            p2 += v[i+2].x * w2.x + v[i+2].y * w2.y + v[i+2].z * w2.z + v[i+2].w * w2.w;
            p3 += v[i+3].x * w3.x + v[i+3].y * w3.y + v[i+3].z * w3.z + v[i+3].w * w3.w;
        }
        float pd = (p0 + p1) + (p2 + p3);
#pragma unroll
        for (int o = 16; o; o >>= 1) pd += __shfl_xor_sync(0xffffffffu, pd, o);

        float e = fmaxf(hdot + pd, 0.f);
        if (e > m) {
            float sc = __expf(m - e);
            l *= sc;
#pragma unroll
            for (int i = 0; i < 16; i++) {
                ctx[i].x *= sc; ctx[i].y *= sc; ctx[i].z *= sc; ctx[i].w *= sc;
            }
            m = e;
        }
        float wgt = __expf(e - m);
        l += wgt;
#pragma unroll
        for (int i = 0; i < 16; i++) {
            ctx[i].x += wgt * v[i].x; ctx[i].y += wgt * v[i].y;
            ctx[i].z += wgt * v[i].z; ctx[i].w += wgt * v[i].w;
        }
    }

    if (lane == 0) { m_s[w] = m; l_s[w] = l; }
    __syncthreads();
    float m_g = -1e30f;
#pragma unroll
    for (int k = 0; k < 8; k++) m_g = fmaxf(m_g, m_s[k]);
    float l_g = 0.f;
#pragma unroll
    for (int k = 0; k < 8; k++) l_g += l_s[k] * __expf(m_s[k] - m_g);
    float coef = __expf(m - m_g) / l_g;

#pragma unroll
    for (int i = 0; i < 8; i++)
        *(float4*)&ctx_s[w][i * 128 + 4 * lane] =
            make_float4(ctx[i].x * coef, ctx[i].y * coef, ctx[i].z * coef, ctx[i].w * coef);
    __syncthreads();
    {
        float4 s4 = make_float4(0.f, 0.f, 0.f, 0.f);
#pragma unroll
        for (int k = 0; k < 8; k++) {
            float4 vv = *(const float4*)&ctx_s[k][4 * t];
            s4.x += vv.x; s4.y += vv.y; s4.z += vv.z; s4.w += vv.w;
        }
        __half2* dst = (__half2*)(d_A1 + b * KA + 4 * t);
        dst[0] = __floats2half2_rn(s4.x, s4.y);
        dst[1] = __floats2half2_rn(s4.z, s4.w);
    }
    __syncthreads();
#pragma unroll
    for (int i = 8; i < 16; i++)
        *(float4*)&ctx_s[w][(i - 8) * 128 + 4 * lane] =
            make_float4(ctx[i].x * coef, ctx[i].y * coef, ctx[i].z * coef, ctx[i].w * coef);
    __syncthreads();
    {
        float4 s4 = make_float4(0.f, 0.f, 0.f, 0.f);
#pragma unroll
        for (int k = 0; k < 8; k++) {
            float4 vv = *(const float4*)&ctx_s[k][4 * t];
            s4.x += vv.x; s4.y += vv.y; s4.z += vv.z; s4.w += vv.w;
        }
        __half2* dst = (__half2*)(d_A1 + b * KA + 1024 + 4 * t);
        dst[0] = __floats2half2_rn(s4.x, s4.y);
        dst[1] = __floats2half2_rn(s4.z, s4.w);
    }

    {
        int tok = x[b];
#pragma unroll
        for (int i = 0; i < 2; i++) {
            int c = t + i * 256;
            d_A1[b * KA + 2048 + c] = __float2half_rn(emb[(size_t)tok * EMBN + c]);
        }
#pragma unroll
        for (int i = 0; i < 4; i++) {
            int c = t + i * 256;
            d_A1[b * KA + 2560 + c] = __float2half_rn(hidden[b * HIDN + c]);
        }
    }
}

// =====================================================================
// gates GEMM + fused LSTM, 512 threads = 2 warp-groups (in-CTA split-K).
// wg0: K chunks 0,2,..,26; wg1: 1,3,..,27 (x128). Each wg has its own
// As/Bs double-staged region (43.5KB x2 = 87KB dynamic). Warp layout
// inside wg: 4m x 2n (R16 proven). Partial merge via smem, LSTM fused.
// =====================================================================
#define GG_AS_BYTES (128 * 136 * 2)   // 34816
#define GG_BS_BYTES (32 * 136 * 2)    // 8704
#define GG_WG_BYTES (GG_AS_BYTES + GG_BS_BYTES)  // 43520
#define GG_SMEM (2 * GG_WG_BYTES)     // 87040

__global__ __launch_bounds__(512, 1) void gemm_gates_lstm(
    const float* __restrict__ Wih, const float* __restrict__ Whh,
    const float* __restrict__ bih, const float* __restrict__ bhh,
    const float* __restrict__ cell,
    float* __restrict__ out_h, float* __restrict__ out_c)
{
    int tid = threadIdx.x;
    int wg = tid >> 8;           // warp-group 0/1
    int wtid = tid & 255;
    int lane = tid & 31, w = wtid >> 5;   // warp-in-wg 0..7
    int wm = w >> 1, wn = w & 1;          // 4m x 2n
    int jblk = blockIdx.x * 8;

    __half (*As)[136] = (__half(*)[136])(dynsm + wg * GG_WG_BYTES);
    __half (*Bs)[136] = (__half(*)[136])(dynsm + wg * GG_WG_BYTES + GG_AS_BYTES);

    const int NST = 14;          // 14 chunks of 128 per wg

    float acc[2][2][4];
#pragma unroll
    for (int a = 0; a < 2; a++)
#pragma unroll
        for (int bq = 0; bq < 2; bq++)
#pragma unroll
            for (int q = 0; q < 4; q++) acc[a][bq][q] = 0.f;

    int aRow[8], aCol[8];
#pragma unroll
    for (int i = 0; i < 8; i++) { int idx = wtid + i * 256; aRow[i] = idx >> 4; aCol[i] = (idx & 15) * 8; }
    int bRow[4], bCol[4], bN[4];
#pragma unroll
    for (int i = 0; i < 4; i++) {
        int idx = wtid + i * 256;
        bRow[i] = idx >> 5; bCol[i] = (idx & 31) * 4;
        bN[i] = (bRow[i] >> 3) * 1024 + jblk + (bRow[i] & 7);
    }

    uint4 aReg[8];
    float4 bReg[4];

    // stage 0: ks = wg*128 (< 2560 -> Wih)
    {
        int ks = wg * 128;
#pragma unroll
        for (int i = 0; i < 8; i++)
            aReg[i] = *(const uint4*)(d_A1 + aRow[i] * KA + ks + aCol[i]);
#pragma unroll
        for (int i = 0; i < 4; i++)
            bReg[i] = *(const float4*)(Wih + (size_t)bN[i] * 2560 + ks + bCol[i]);
    }
#pragma unroll
    for (int i = 0; i < 8; i++) *(uint4*)&As[aRow[i]][aCol[i]] = aReg[i];
#pragma unroll
    for (int i = 0; i < 4; i++) {
        *(__half2*)&Bs[bRow[i]][bCol[i]]     = __floats2half2_rn(bReg[i].x, bReg[i].y);
        *(__half2*)&Bs[bRow[i]][bCol[i] + 2] = __floats2half2_rn(bReg[i].z, bReg[i].w);
    }
    __syncthreads();

    for (int st = 0; st < NST; ++st) {
        if (st + 1 < NST) {
            int ks = (2 * (st + 1) + wg) * 128;
#pragma unroll
            for (int i = 0; i < 8; i++)
                aReg[i] = *(const uint4*)(d_A1 + aRow[i] * KA + ks + aCol[i]);
            if (ks < 2560) {
#pragma unroll
                for (int i = 0; i < 4; i++)
                    bReg[i] = *(const float4*)(Wih + (size_t)bN[i] * 2560 + ks + bCol[i]);
            } else {
#pragma unroll
                for (int i = 0; i < 4; i++)
                    bReg[i] = *(const float4*)(Whh + (size_t)bN[i] * 1024 + (ks - 2560) + bCol[i]);
            }
        }
#pragma unroll
        for (int kk = 0; kk < 128; kk += 16) {
            uint32_t af[2][4], bf[2][2];
#pragma unroll
            for (int mi = 0; mi < 2; mi++) {
                int r = wm * 32 + mi * 16 + (lane & 7) + ((lane >> 3) & 1) * 8;
                int c = kk + (lane >> 4) * 8;
                ldmx4(af[mi][0], af[mi][1], af[mi][2], af[mi][3], smem_addr(&As[r][c]));
            }
            {
                int r = wn * 16 + (lane >> 4) * 8 + (lane & 7);
                int c = kk + ((lane >> 3) & 1) * 8;
                ldmx4(bf[0][0], bf[0][1], bf[1][0], bf[1][1], smem_addr(&Bs[r][c]));
            }
#pragma unroll
            for (int mi = 0; mi < 2; mi++)
#pragma unroll
                for (int ni = 0; ni < 2; ni++)
                    mma16816(acc[mi][ni], af[mi], bf[ni]);
        }
        __syncthreads();
        if (st + 1 < NST) {
#pragma unroll
            for (int i = 0; i < 8; i++) *(uint4*)&As[aRow[i]][aCol[i]] = aReg[i];
#pragma unroll
            for (int i = 0; i < 4; i++) {
                *(__half2*)&Bs[bRow[i]][bCol[i]]     = __floats2half2_rn(bReg[i].x, bReg[i].y);
                *(__half2*)&Bs[bRow[i]][bCol[i] + 2] = __floats2half2_rn(bReg[i].z, bReg[i].w);
            }
            __syncthreads();
        }
    }

    // ---- merge: wg1 stages its partials; wg0 adds + bias into gsm ----
    float (*gsm)[36] = (float(*)[36])dynsm;              // 18.4KB
    float* part = (float*)(dynsm + 24576);               // 16KB, conflict-free layout

    if (wg == 1) {
#pragma unroll
        for (int mi = 0; mi < 2; mi++)
#pragma unroll
            for (int ni = 0; ni < 2; ni++) {
                int c = mi * 2 + ni;
                *(float4*)&part[((w * 4 + c) * 32 + lane) * 4] =
                    make_float4(acc[mi][ni][0], acc[mi][ni][1], acc[mi][ni][2], acc[mi][ni][3]);
            }
    }
    __syncthreads();

    if (wg == 0) {
        int jl0 = (lane & 3) * 2;
#pragma unroll
        for (int mi = 0; mi < 2; mi++)
#pragma unroll
            for (int ni = 0; ni < 2; ni++) {
                int c = mi * 2 + ni;
                float4 p = *(const float4*)&part[((w * 4 + c) * 32 + lane) * 4];
                int mrow = wm * 32 + mi * 16 + (lane >> 2);
                int n32 = wn * 16 + ni * 8 + jl0;
                int gate = wn * 2 + ni;
                float b0 = bih[gate * 1024 + jblk + jl0]     + bhh[gate * 1024 + jblk + jl0];
                float b1 = bih[gate * 1024 + jblk + jl0 + 1] + bhh[gate * 1024 + jblk + jl0 + 1];
                gsm[mrow][n32]          = acc[mi][ni][0] + p.x + b0;
                gsm[mrow][n32 + 1]      = acc[mi][ni][1] + p.y + b1;
                gsm[mrow + 8][n32]      = acc[mi][ni][2] + p.z + b0;
                gsm[mrow + 8][n32 + 1]  = acc[mi][ni][3] + p.w + b1;
            }
    }
    __syncthreads();

    // ---- fused LSTM: 1024 elements, 2 per thread across 512 threads ----
    {
        int idx = tid * 2;
        int b = idx >> 3;
        int jj0 = idx & 7;     // 0,2,4,6
        float2 ig = *(const float2*)&gsm[b][0 + jj0];
        float2 fg = *(const float2*)&gsm[b][8 + jj0];
        float2 gg = *(const float2*)&gsm[b][16 + jj0];
        float2 og = *(const float2*)&gsm[b][24 + jj0];
        float2 co = *(const float2*)(cell + b * HIDN + jblk + jj0);
        float igv[2] = {ig.x, ig.y}, fgv[2] = {fg.x, fg.y};
        float ggv[2] = {gg.x, gg.y}, ogv[2] = {og.x, og.y};
        float cov[2] = {co.x, co.y};
        float h[2], c[2];
#pragma unroll
        for (int i = 0; i < 2; i++) {
            float is = 1.f / (1.f + __expf(-igv[i]));
            float fs = 1.f / (1.f + __expf(-fgv[i]));
            float gt = tanhf(ggv[i]);
            float os = 1.f / (1.f + __expf(-ogv[i]));
            c[i] = fs * cov[i] + is * gt;
            h[i] = os * tanhf(c[i]);
        }
        *(float2*)(out_c + b * HIDN + jblk + jj0) = make_float2(c[0], c[1]);
        *(float2*)(out_h + b * HIDN + jblk + jj0) = make_float2(h[0], h[1]);
        *(__half2*)(d_hnew + b * HIDN + jblk + jj0) = __floats2half2_rn(h[0], h[1]);
    }
}

// =====================================================================
// fc GEMM (R9 proven): 128x128 tile, KC=32, cp.async 3-slot ring,
// 2 CTAs/SM, convert-own-data + Bs ping-pong, 1 barrier/stage.
// =====================================================================
#define FC_KC 32
#define FC_NST (HIDN / FC_KC)          // 32
#define FC_AS_HALFS (128 * 40)
#define FC_BR_FLOATS (128 * FC_KC)
#define FC_BS_HALFS (128 * 40)
#define FC_SMEM (3 * FC_AS_HALFS * 2 + 3 * FC_BR_FLOATS * 4 + 2 * FC_BS_HALFS * 2)

__device__ __forceinline__ void fc_issue_stage(int s, int ks, int nblk, int tid,
                                               const float* W)
{
    __half* AsS = (__half*)dynsm + (s % 3) * FC_AS_HALFS;
    float* BrS  = (float*)(dynsm + 3 * FC_AS_HALFS * 2) + (s % 3) * FC_BR_FLOATS;
#pragma unroll
    for (int i = 0; i < 2; i++) {
        int idx = tid + i * 256;
        int row = idx >> 2, ch = idx & 3;
        cp_async16(smem_addr(AsS + row * 40 + ch * 8),
                   d_hnew + row * HIDN + ks + ch * 8);
    }
#pragma unroll
    for (int i = 0; i < 4; i++) {
        int idx = tid + i * 256;
        int row = idx >> 3, ch = idx & 7;
        cp_async16(smem_addr(BrS + row * FC_KC + ch * 4),
                   W + (size_t)(nblk + row) * HIDN + ks + ch * 4);
    }
}

__global__ __launch_bounds__(256, 2) void gemm_fc(
    const float* __restrict__ W, const float* __restrict__ bias, float* __restrict__ out)
{
    int tid = threadIdx.x, lane = tid & 31, w = tid >> 5;
    int wm = w >> 2, wn = w & 3;
    int nblk = blockIdx.x * 128;

    __half* BsBase = (__half*)(dynsm + 3 * FC_AS_HALFS * 2 + 3 * FC_BR_FLOATS * 4);

    float acc[4][4][4];
#pragma unroll
    for (int a = 0; a < 4; a++)
#pragma unroll
        for (int bq = 0; bq < 4; bq++)
#pragma unroll
            for (int cq = 0; cq < 4; cq++) acc[a][bq][cq] = 0.f;

    fc_issue_stage(0, 0, nblk, tid, W);
    cp_commit();
    fc_issue_stage(1, FC_KC, nblk, tid, W);
    cp_commit();

    for (int st = 0; st < FC_NST; ++st) {
        cp_wait<1>();

        {
            const float* BrS = (const float*)(dynsm + 3 * FC_AS_HALFS * 2) + (st % 3) * FC_BR_FLOATS;
            __half* BsS = BsBase + (st & 1) * FC_BS_HALFS;
#pragma unroll
            for (int i = 0; i < 4; i++) {
                int idx = tid + i * 256;
                int row = idx >> 3, ch = idx & 7;
                float4 v = *(const float4*)(BrS + row * FC_KC + ch * 4);
                __half2 h0 = __floats2half2_rn(v.x, v.y);
                __half2 h1 = __floats2half2_rn(v.z, v.w);
                uint32_t u0 = *(uint32_t*)&h0, u1 = *(uint32_t*)&h1;
                uint2 packed = make_uint2(u0, u1);
                *(uint2*)(BsS + row * 40 + ch * 4) = packed;
            }
        }
        __syncthreads();

        if (st + 2 < FC_NST)
            fc_issue_stage(st + 2, (st + 2) * FC_KC, nblk, tid, W);
        cp_commit();

        const __half (*As)[40] = (const __half(*)[40])((__half*)dynsm + (st % 3) * FC_AS_HALFS);
        const __half (*Bs)[40] = (const __half(*)[40])(BsBase + (st & 1) * FC_BS_HALFS);
#pragma unroll
        for (int kk = 0; kk < FC_KC; kk += 16) {
            uint32_t af[4][4], bf[4][2];
#pragma unroll
            for (int mi = 0; mi < 4; mi++) {
                int r = wm * 64 + mi * 16 + (lane & 7) + ((lane >> 3) & 1) * 8;
                int c = kk + (lane >> 4) * 8;
                ldmx4(af[mi][0], af[mi][1], af[mi][2], af[mi][3], smem_addr(&As[r][c]));
            }
#pragma unroll
            for (int np = 0; np < 2; np++) {
                int r = wn * 32 + np * 16 + (lane >> 4) * 8 + (lane & 7);
                int c = kk + ((lane >> 3) & 1) * 8;
                ldmx4(bf[2 * np][0], bf[2 * np][1], bf[2 * np + 1][0], bf[2 * np + 1][1],
                      smem_addr(&Bs[r][c]));
            }
#pragma unroll
            for (int mi = 0; mi < 4; mi++)
#pragma unroll
                for (int ni = 0; ni < 4; ni++)
                    mma16816(acc[mi][ni], af[mi], bf[ni]);
        }
    }
    __syncthreads();

    float (*Cs)[132] = (float(*)[132])dynsm;
#pragma unroll
    for (int mi = 0; mi < 4; mi++)
#pragma unroll
        for (int ni = 0; ni < 4; ni++) {
            int mrow = wm * 64 + mi * 16 + (lane >> 2);
            int nl = wn * 32 + ni * 8 + (lane & 3) * 2;
            float b0 = bias[nblk + nl], b1 = bias[nblk + nl + 1];
            Cs[mrow][nl]          = acc[mi][ni][0] + b0;
            Cs[mrow][nl + 1]      = acc[mi][ni][1] + b1;
            Cs[mrow + 8][nl]      = acc[mi][ni][2] + b0;
            Cs[mrow + 8][nl + 1]  = acc[mi][ni][3] + b1;
        }
    __syncthreads();
#pragma unroll
    for (int it = 0; it < 4; it++) {
        int row = it * 32 + (tid >> 3);
#pragma unroll
        for (int j = 0; j < 4; j++) {
            int c4 = (tid & 7) + 8 * j;
            float4 v = *(const float4*)&Cs[row][c4 * 4];
            *(float4*)(out + (size_t)row * VOCABN + nblk + c4 * 4) = v;
        }
    }
}

// =====================================================================
extern "C" void kernel_launch(void* const* d_in, const int* in_sizes, int n_in,
                              void* d_out, int out_size)
{
    const int*   x      = (const int*)d_in[0];
    const float* enc    = (const float*)d_in[1];
    const float* hidden = (const float*)d_in[2];
    const float* cell   = (const float*)d_in[3];
    const float* emb    = (const float*)d_in[4];
    const float* We     = (const float*)d_in[5];
    const float* be     = (const float*)d_in[6];
    const float* Wih    = (const float*)d_in[7];
    const float* Whh    = (const float*)d_in[8];
    const float* bih    = (const float*)d_in[9];
    const float* bhh    = (const float*)d_in[10];
    const float* Wfc    = (const float*)d_in[11];
    const float* bfc    = (const float*)d_in[12];
    float* out = (float*)d_out;

    const size_t PRED = (size_t)BATCHN * VOCABN;
    float* out_h = out + PRED;
    float* out_c = out + PRED + (size_t)BATCHN * HIDN;

    cudaFuncSetAttribute(gemm_gates_lstm, cudaFuncAttributeMaxDynamicSharedMemorySize, GG_SMEM);
    cudaFuncSetAttribute(gemm_fc, cudaFuncAttributeMaxDynamicSharedMemorySize, FC_SMEM);

    // 2 noops so gemm_gates_lstm lands in the profiled 4th-launch slot
    noop_kernel<<<1, 32>>>();
    noop_kernel<<<1, 32>>>();
    attn_kernel<<<BATCHN, 256>>>(enc, hidden, We, be, x, emb);
    gemm_gates_lstm<<<HIDN / 8, 512, GG_SMEM>>>(Wih, Whh, bih, bhh, cell, out_h, out_c);
    gemm_fc<<<VOCABN / 128, 256, FC_SMEM>>>(Wfc, bfc, out);
}